// round 8
// baseline (speedup 1.0000x reference)
#include <cuda_runtime.h>
#include <math.h>
#include <stdint.h>

#define BB 256
#define TT 32
#define SS 128
#define II 256
#define HH 1024
#define OO 256
#define G4 4096

// ---------------- scratch (static device globals; no allocation) ------------
__device__ float d_Xg[(size_t)TT * BB * G4];   // [T][B][4H] input gates + biases
__device__ float d_h[2][BB * HH];              // double-buffered hidden (fp32)
__device__ uint32_t d_ht32[2][BB * HH];        // hidden, tf32 fragment-permuted
__device__ float d_c[BB * HH];
__device__ float d_u[2][BB * 2 * HH];          // double-buffered [ctx|h] for FC
__device__ float d_fcp[2][4][BB * OO];         // split-K FC partials
__device__ uint32_t d_Wih_t[G4 * II];          // tf32 (plain layout)
__device__ uint32_t d_Whh_t[(size_t)G4 * HH];  // tf32, fragment-permuted in k8 groups
__device__ uint32_t d_Wfc_t[OO * 2 * HH];      // tf32 (plain layout)

// ---------------- helpers ----------------------------------------------------
__device__ __forceinline__ uint32_t f2tf32(float x) {
    uint32_t r;
    asm("cvt.rna.tf32.f32 %0, %1;" : "=r"(r) : "f"(x));
    return r;
}
__device__ __forceinline__ uint32_t cvta_s(const void* p) {
    return (uint32_t)__cvta_generic_to_shared(p);
}
// permute k within its 8-group so (k, k+4) become adjacent
__device__ __forceinline__ int kperm(int k) {
    return (k & ~7) + ((k & 3) << 1) + ((k >> 2) & 1);
}
#define CPASYNC16(sa, g) asm volatile("cp.async.cg.shared.global [%0], [%1], 16;" :: "r"(sa), "l"(g))
#define CPASYNC16Z(sa, g, sz) asm volatile("cp.async.cg.shared.global [%0], [%1], 16, %2;" :: "r"(sa), "l"(g), "r"(sz))
#define CPCOMMIT() asm volatile("cp.async.commit_group;")
#define CPWAIT(n) asm volatile("cp.async.wait_group %0;" :: "n"(n))

__device__ __forceinline__ void mma_tf32(float c[4], const uint32_t a[4], const uint32_t b[2]) {
    asm volatile(
        "mma.sync.aligned.m16n8k8.row.col.f32.tf32.tf32.f32 "
        "{%0,%1,%2,%3}, {%4,%5,%6,%7}, {%8,%9}, {%0,%1,%2,%3};"
        : "+f"(c[0]), "+f"(c[1]), "+f"(c[2]), "+f"(c[3])
        : "r"(a[0]), "r"(a[1]), "r"(a[2]), "r"(a[3]), "r"(b[0]), "r"(b[1]));
}

#define SIG(x) (1.f / (1.f + __expf(-(x))))

// ========== precompute GEMM (k_pre): 128x128 tiles, depth-2 ==================
__device__ __forceinline__ void gemm_pre(
    int ctam, int ctan,
    const float* __restrict__ Ag, const uint32_t* __restrict__ Bt,
    const float* __restrict__ e1, const float* __restrict__ e2,
    float* __restrict__ Cout, int K, char* dyn)
{
    float* As = (float*)dyn;
    uint32_t* Bs = (uint32_t*)(dyn + 36864);
    const int tid = threadIdx.x;
    const int lane = tid & 31;
    const int wid = tid >> 5;
    const int wm = wid & 3;
    const int wn = wid >> 2;
    const int tg = lane & 3;
    const int gpr = lane >> 2;

    float acc[2][8][4];
#pragma unroll
    for (int i = 0; i < 2; ++i)
#pragma unroll
        for (int j = 0; j < 8; ++j)
#pragma unroll
            for (int k = 0; k < 4; ++k) acc[i][j][k] = 0.f;

    const int nc = K >> 5;
    auto stage = [&](int buf, int kc) {
#pragma unroll
        for (int it = 0; it < 4; ++it) {
            int slot = it * 256 + tid;
            int row = slot >> 3;
            int cc = (slot & 7) << 2;
            uint32_t sa = cvta_s(As + buf * 4608 + row * 36 + cc);
            int m = ctam * 128 + row;
            int t_ = m >> 8;
            int b_ = m & 255;
            const float* ga = (t_ == 0) ? Ag : Ag + ((size_t)b_ * TT + t_) * II + kc + cc;
            int sz = (t_ == 0) ? 0 : 16;
            CPASYNC16Z(sa, ga, sz);
            uint32_t sb = cvta_s(Bs + buf * 4608 + row * 36 + cc);
            CPASYNC16(sb, Bt + (size_t)(ctan * 128 + row) * K + kc + cc);
        }
    };

    stage(0, 0);
    CPCOMMIT();
    for (int c = 0; c < nc; ++c) {
        if (c + 1 < nc) stage((c + 1) & 1, (c + 1) * 32);
        CPCOMMIT();
        CPWAIT(1);
        __syncthreads();
        const float* Af = As + (c & 1) * 4608;
        const uint32_t* Bf = Bs + (c & 1) * 4608;
#pragma unroll
        for (int ks = 0; ks < 4; ++ks) {
            uint32_t a[2][4], b[8][2];
#pragma unroll
            for (int mt = 0; mt < 2; ++mt) {
                int r = wm * 32 + mt * 16 + gpr;
                a[mt][0] = f2tf32(Af[r * 36 + ks * 8 + tg]);
                a[mt][1] = f2tf32(Af[(r + 8) * 36 + ks * 8 + tg]);
                a[mt][2] = f2tf32(Af[r * 36 + ks * 8 + tg + 4]);
                a[mt][3] = f2tf32(Af[(r + 8) * 36 + ks * 8 + tg + 4]);
            }
#pragma unroll
            for (int nt = 0; nt < 8; ++nt) {
                int n = wn * 64 + nt * 8 + gpr;
                b[nt][0] = Bf[n * 36 + ks * 8 + tg];
                b[nt][1] = Bf[n * 36 + ks * 8 + tg + 4];
            }
#pragma unroll
            for (int mt = 0; mt < 2; ++mt)
#pragma unroll
                for (int nt = 0; nt < 8; ++nt)
                    mma_tf32(acc[mt][nt], a[mt], b[nt]);
        }
        __syncthreads();
    }
#pragma unroll
    for (int mt = 0; mt < 2; ++mt)
#pragma unroll
        for (int nt = 0; nt < 8; ++nt) {
            int gm0 = ctam * 128 + wm * 32 + mt * 16 + gpr;
            int gn = ctan * 128 + wn * 64 + nt * 8 + tg * 2;
#pragma unroll
            for (int half = 0; half < 2; ++half) {
                int gm = gm0 + half * 8;
                float v0 = acc[mt][nt][half * 2 + 0] + e1[gn] + e2[gn];
                float v1 = acc[mt][nt][half * 2 + 1] + e1[gn + 1] + e2[gn + 1];
                *(float2*)(Cout + (size_t)gm * G4 + gn) = make_float2(v0, v1);
            }
        }
}

// ========== fused gates GEMM + LSTM cell: fat CTAs, 0.75 LDS.64/mma ==========
// 64 CTAs = ctam(2) x ctan(32). CTA tile 128M x 128N (4 gates x 32 cols).
// Warp tile 32M x 64N (wm 0..3, wn 0..1; mt=2, nt=8). K=1024, chunk 32, depth 2.
// smem: As u32 [2][128][40] @0 (40960 B), Bs u32 [2][128][40] @40960 -> 81920 B.
// stride 40 words: 40%32=8 -> fragment LDS.64 conflict-free.
// Epilogue reuse: ep fp32 [128][132] @0 (67584 B).
__device__ __forceinline__ void gatescell_dev(
    int ctam, int ctan,
    const uint32_t* __restrict__ hA,   // h_{t-1}, tf32 permuted
    const float* __restrict__ Xg,      // d_Xg + t*BB*G4
    float* __restrict__ hOut,          // h_t fp32
    uint32_t* __restrict__ hOut32,     // h_t tf32 permuted
    char* dyn)
{
    uint32_t* As = (uint32_t*)dyn;
    uint32_t* Bs = (uint32_t*)(dyn + 40960);
    const int tid = threadIdx.x;
    const int lane = tid & 31;
    const int wid = tid >> 5;
    const int wm = wid & 3;      // 4 M slices of 32 rows
    const int wn = wid >> 2;     // 2 N halves of 64 cols
    const int tg = lane & 3;
    const int gpr = lane >> 2;
    const int q0 = ctan * 32;
    const int m0 = ctam * 128;

    float acc[2][8][4];
#pragma unroll
    for (int i = 0; i < 2; ++i)
#pragma unroll
        for (int j = 0; j < 8; ++j)
#pragma unroll
            for (int k = 0; k < 4; ++k) acc[i][j][k] = 0.f;

    auto stage = [&](int buf, int kc) {
        // A: 128x32 u32 = 1024 x 16B, 4 per thread
#pragma unroll
        for (int it = 0; it < 4; ++it) {
            int slot = it * 256 + tid;
            int row = slot >> 3;
            int cc = (slot & 7) << 2;
            CPASYNC16(cvta_s(As + buf * 5120 + row * 40 + cc),
                      hA + (size_t)(m0 + row) * HH + kc + cc);
        }
        // B: 128x32 u32; rows gather 4 gate blocks of 32
#pragma unroll
        for (int it = 0; it < 4; ++it) {
            int slot = it * 256 + tid;
            int row = slot >> 3;
            int cc = (slot & 7) << 2;
            int wr = (row >> 5) * HH + q0 + (row & 31);
            CPASYNC16(cvta_s(Bs + buf * 5120 + row * 40 + cc),
                      d_Whh_t + (size_t)wr * HH + kc + cc);
        }
    };

    stage(0, 0); CPCOMMIT();
    const int nc = 32;  // 1024 / 32
    for (int c = 0; c < nc; ++c) {
        if (c + 1 < nc) stage((c + 1) & 1, (c + 1) * 32);
        CPCOMMIT();
        CPWAIT(1);
        __syncthreads();
        const uint32_t* Af = As + (c & 1) * 5120;
        const uint32_t* Bf = Bs + (c & 1) * 5120;
#pragma unroll
        for (int ks = 0; ks < 4; ++ks) {
            uint32_t a[2][4], b[8][2];
#pragma unroll
            for (int mt = 0; mt < 2; ++mt) {
                int r = wm * 32 + mt * 16 + gpr;
                uint2 lo = *(const uint2*)(Af + r * 40 + ks * 8 + tg * 2);
                uint2 hi = *(const uint2*)(Af + (r + 8) * 40 + ks * 8 + tg * 2);
                a[mt][0] = lo.x; a[mt][2] = lo.y;
                a[mt][1] = hi.x; a[mt][3] = hi.y;
            }
#pragma unroll
            for (int nt = 0; nt < 8; ++nt) {
                int n = wn * 64 + nt * 8 + gpr;
                uint2 v = *(const uint2*)(Bf + n * 40 + ks * 8 + tg * 2);
                b[nt][0] = v.x; b[nt][1] = v.y;
            }
#pragma unroll
            for (int mt = 0; mt < 2; ++mt)
#pragma unroll
                for (int nt = 0; nt < 8; ++nt)
                    mma_tf32(acc[mt][nt], a[mt], b[nt]);
        }
        __syncthreads();
    }

    // gate exchange: ep[row 128][n 128], stride 132
    float* ep = (float*)dyn;
    __syncthreads();
#pragma unroll
    for (int mt = 0; mt < 2; ++mt)
#pragma unroll
        for (int nt = 0; nt < 8; ++nt) {
            int r0 = wm * 32 + mt * 16 + gpr;
            int col = wn * 64 + nt * 8 + tg * 2;
            *(float2*)(ep + r0 * 132 + col) = make_float2(acc[mt][nt][0], acc[mt][nt][1]);
            *(float2*)(ep + (r0 + 8) * 132 + col) = make_float2(acc[mt][nt][2], acc[mt][nt][3]);
        }
    __syncthreads();

    // cell: 128 rows x 32 q = 4096 elems, 16 per thread
#pragma unroll
    for (int k = 0; k < 16; ++k) {
        int idx = k * 256 + tid;
        int row = idx >> 5;
        int qq = idx & 31;
        int b = m0 + row;
        int q = q0 + qq;
        size_t xb = (size_t)b * G4 + q;
        float vi = ep[row * 132 + qq]        + Xg[xb];
        float vf = ep[row * 132 + 32 + qq]   + Xg[xb + HH];
        float vg = ep[row * 132 + 64 + qq]   + Xg[xb + 2 * HH];
        float vo = ep[row * 132 + 96 + qq]   + Xg[xb + 3 * HH];
        size_t hb = (size_t)b * HH + q;
        float c_old = d_c[hb];
        float c_new = SIG(vf) * c_old + SIG(vi) * tanhf(vg);
        float h_new = SIG(vo) * tanhf(c_new);
        d_c[hb] = c_new;
        hOut[hb] = h_new;
        hOut32[(size_t)b * HH + kperm(q)] = f2tf32(h_new);
    }
}

// ========== FC split-K partial GEMM ==========================================
__device__ __forceinline__ void fcpart_dev(
    int ctam, int ctan, int kslice,
    const float* __restrict__ u, float* __restrict__ part)
{
    extern __shared__ char dyn[];
    float* Af = (float*)dyn;
    uint32_t* Bf = (uint32_t*)(dyn + 55296);
    const int tid = threadIdx.x;
    const int lane = tid & 31;
    const int wid = tid >> 5;
    const int wm = wid & 3;
    const int wn = wid >> 2;
    const int tg = lane & 3;
    const int gpr = lane >> 2;
    const int k0 = kslice * 512;

    float acc[2][4][4];
#pragma unroll
    for (int i = 0; i < 2; ++i)
#pragma unroll
        for (int j = 0; j < 4; ++j)
#pragma unroll
            for (int k = 0; k < 4; ++k) acc[i][j][k] = 0.f;

    auto stage = [&](int buf, int kc) {
#pragma unroll
        for (int it = 0; it < 4; ++it) {
            int slot = it * 256 + tid;
            int row = slot >> 3;
            int cc = (slot & 7) << 2;
            CPASYNC16(cvta_s(Af + buf * 4608 + row * 36 + cc),
                      u + (size_t)(ctam * 128 + row) * (2 * HH) + k0 + kc + cc);
        }
#pragma unroll
        for (int it = 0; it < 2; ++it) {
            int slot = it * 256 + tid;
            int row = slot >> 3;
            int cc = (slot & 7) << 2;
            CPASYNC16(cvta_s(Bf + buf * 2304 + row * 36 + cc),
                      d_Wfc_t + (size_t)(ctan * 64 + row) * (2 * HH) + k0 + kc + cc);
        }
    };

    stage(0, 0); CPCOMMIT();
    stage(1, 32); CPCOMMIT();
    const int nc = 16;
    for (int c = 0; c < nc; ++c) {
        if (c + 2 < nc) stage((c + 2) % 3, (c + 2) * 32);
        CPCOMMIT();
        CPWAIT(2);
        __syncthreads();
        const float* A = Af + (c % 3) * 4608;
        const uint32_t* B = Bf + (c % 3) * 2304;
#pragma unroll
        for (int kk = 0; kk < 4; ++kk) {
            uint32_t a[2][4], b[4][2];
#pragma unroll
            for (int mt = 0; mt < 2; ++mt) {
                int r = wm * 32 + mt * 16 + gpr;
                a[mt][0] = f2tf32(A[r * 36 + kk * 8 + tg]);
                a[mt][1] = f2tf32(A[(r + 8) * 36 + kk * 8 + tg]);
                a[mt][2] = f2tf32(A[r * 36 + kk * 8 + tg + 4]);
                a[mt][3] = f2tf32(A[(r + 8) * 36 + kk * 8 + tg + 4]);
            }
#pragma unroll
            for (int nt = 0; nt < 4; ++nt) {
                int n = wn * 32 + nt * 8 + gpr;
                b[nt][0] = B[n * 36 + kk * 8 + tg];
                b[nt][1] = B[n * 36 + kk * 8 + tg + 4];
            }
#pragma unroll
            for (int mt = 0; mt < 2; ++mt)
#pragma unroll
                for (int nt = 0; nt < 4; ++nt)
                    mma_tf32(acc[mt][nt], a[mt], b[nt]);
        }
        __syncthreads();
    }
#pragma unroll
    for (int mt = 0; mt < 2; ++mt)
#pragma unroll
        for (int nt = 0; nt < 4; ++nt) {
            int gm0 = ctam * 128 + wm * 32 + mt * 16 + gpr;
            int gn = ctan * 64 + wn * 32 + nt * 8 + tg * 2;
            *(float2*)(part + (size_t)gm0 * OO + gn) =
                make_float2(acc[mt][nt][0], acc[mt][nt][1]);
            *(float2*)(part + (size_t)(gm0 + 8) * OO + gn) =
                make_float2(acc[mt][nt][2], acc[mt][nt][3]);
        }
}

// ========== attention (cp.async pipelined single-pass softmax) ================
__device__ __forceinline__ void attn_dev(int b, int tatt, const float* __restrict__ enc,
                                         const float* __restrict__ hcur,
                                         float* __restrict__ out, int par, char* dyn,
                                         float* s_scores, float* s_m, float* s_l)
{
    float* es = (float*)dyn;
    const int tid = threadIdx.x;
    const int lane = tid & 31;
    const int w = tid >> 5;

    const float* hb = hcur + (size_t)b * HH;
    float hreg[32];
#pragma unroll
    for (int i = 0; i < 32; ++i) hreg[i] = hb[i * 32 + lane];

    const float* encb = enc + (size_t)b * SS * HH;
#pragma unroll
    for (int p = 0; p < 3; ++p) {
        const float* gsrc = encb + (size_t)(w * 16 + p) * HH;
        float* sb = es + ((size_t)(p % 3) * 8 + w) * 1024;
#pragma unroll
        for (int q = 0; q < 8; ++q)
            CPASYNC16(cvta_s(sb + q * 128 + lane * 4), gsrc + q * 128 + lane * 4);
        CPCOMMIT();
    }

    float m = -1e30f, l = 0.f;
    float ctx[32];
#pragma unroll
    for (int i = 0; i < 32; ++i) ctx[i] = 0.f;

    for (int j = 0; j < 16; ++j) {
        CPWAIT(2);
        __syncwarp();
        const float* e = es + ((size_t)(j % 3) * 8 + w) * 1024;
        float dot = 0.f;
#pragma unroll
        for (int i = 0; i < 32; ++i) dot += hreg[i] * e[i * 32 + lane];
#pragma unroll
        for (int o = 16; o; o >>= 1) dot += __shfl_xor_sync(0xffffffffu, dot, o);
        if (lane == 0) s_scores[w * 16 + j] = dot;

        float nm = fmaxf(m, dot);
        float al = __expf(m - nm);
        float p = __expf(dot - nm);
        l = l * al + p;
#pragma unroll
        for (int i = 0; i < 32; ++i) ctx[i] = ctx[i] * al + p * e[i * 32 + lane];
        m = nm;
        __syncwarp();
        if (j + 3 < 16) {
            const float* gsrc = encb + (size_t)(w * 16 + j + 3) * HH;
            float* sb = es + ((size_t)(j % 3) * 8 + w) * 1024;
#pragma unroll
            for (int q = 0; q < 8; ++q)
                CPASYNC16(cvta_s(sb + q * 128 + lane * 4), gsrc + q * 128 + lane * 4);
        }
        CPCOMMIT();
    }
    CPWAIT(0);
    if (lane == 0) { s_m[w] = m; s_l[w] = l; }
    __syncthreads();

    float M = -1e30f;
#pragma unroll
    for (int i = 0; i < 8; ++i) M = fmaxf(M, s_m[i]);
    float L = 0.f;
#pragma unroll
    for (int i = 0; i < 8; ++i) L += s_l[i] * __expf(s_m[i] - M);

    float sc = __expf(m - M);
    float* cs = es + (size_t)w * 1024;
#pragma unroll
    for (int i = 0; i < 32; ++i) cs[i * 32 + lane] = ctx[i] * sc;
    __syncthreads();

    float* ubuf = d_u[par];
    for (int kk = tid; kk < HH; kk += 256) {
        float sum = 0.f;
#pragma unroll
        for (int ww = 0; ww < 8; ++ww) sum += es[(size_t)ww * 1024 + kk];
        ubuf[(size_t)b * 2 * HH + kk] = sum / L;
        ubuf[(size_t)b * 2 * HH + HH + kk] = hb[kk];
    }
    if (tid < SS) {
        float p = __expf(s_scores[tid] - M) / L;
        out[(size_t)BB * TT * OO + (size_t)b * TT * SS + (size_t)tatt * SS + tid] = p;
    }
}

// ---------------- kernels -----------------------------------------------------
__global__ void k_init() {
    int g = blockIdx.x * 256 + threadIdx.x;  // 65536 float4s per array
    float4 z = make_float4(0.f, 0.f, 0.f, 0.f);
    ((float4*)d_h[1])[g] = z;
    ((float4*)d_ht32[1])[g] = z;
    ((float4*)d_c)[g] = z;
}

__global__ void __launch_bounds__(256) k_convert(const float* __restrict__ Wih,
                                                 const float* __restrict__ Whh,
                                                 const float* __restrict__ Wfc) {
    int g = blockIdx.x * 256 + threadIdx.x;
    int stride = gridDim.x * 256;
    for (int i = g; i < G4 * II; i += stride) d_Wih_t[i] = f2tf32(Wih[i]);
    for (int i = g; i < G4 * HH; i += stride) {
        int n = i >> 10;
        int k = i & 1023;
        d_Whh_t[(size_t)n * HH + kperm(k)] = f2tf32(Whh[i]);
    }
    for (int i = g; i < OO * 2 * HH; i += stride) d_Wfc_t[i] = f2tf32(Wfc[i]);
}

__global__ void __launch_bounds__(256, 2) k_pre(const float* __restrict__ st,
                                                const float* __restrict__ bih,
                                                const float* __restrict__ bhh) {
    extern __shared__ char dyn[];
    gemm_pre(blockIdx.x >> 5, blockIdx.x & 31, st, d_Wih_t, bih, bhh, d_Xg, II, dyn);
}

__global__ void __launch_bounds__(256, 2) kA(int t, int nG, int nA, int nP,
                                             const float* __restrict__ enc,
                                             const float* __restrict__ bfc,
                                             float* __restrict__ out) {
    extern __shared__ char dyn[];
    __shared__ float s_scores[SS];
    __shared__ float s_m[8], s_l[8];
    int bid = blockIdx.x;
    if (bid < nG) {
        // fused gates GEMM + cell for step t (64 fat CTAs)
        gatescell_dev(bid >> 5, bid & 31,
                      d_ht32[(t + 1) & 1], d_Xg + (size_t)t * BB * G4,
                      d_h[t & 1], d_ht32[t & 1], dyn);
    } else if (bid < nG + nA) {
        // attention for step t-1: one batch per CTA
        int ta = t - 1;
        attn_dev(bid - nG, ta, enc, d_h[ta & 1], out, ta & 1, dyn, s_scores, s_m, s_l);
    } else if (bid < nG + nA + nP) {
        int f = bid - nG - nA;     // 0..31
        int tfc = t - 2;
        int ks = f & 3;
        int ctan = (f >> 2) & 3;
        int ctam = f >> 4;
        fcpart_dev(ctam, ctan, ks, d_u[tfc & 1], d_fcp[tfc & 1][ks]);
    } else {
        int tr = t - 3;
        const float* p0 = d_fcp[tr & 1][0];
        const float* p1 = d_fcp[tr & 1][1];
        const float* p2 = d_fcp[tr & 1][2];
        const float* p3 = d_fcp[tr & 1][3];
        int bidr = bid - nG - nA - nP;  // 0..15
        for (int e = bidr * 256 + threadIdx.x; e < BB * OO; e += 16 * 256) {
            int b = e >> 8;
            int o = e & 255;
            float v = p0[e] + p1[e] + p2[e] + p3[e] + bfc[o];
            out[(size_t)b * TT * OO + (size_t)tr * OO + o] = v;
        }
    }
}

// ---------------- launch --------------------------------------------------------
extern "C" void kernel_launch(void* const* d_in, const int* in_sizes, int n_in,
                              void* d_out, int out_size) {
    const float* st  = (const float*)d_in[0];
    const float* enc = (const float*)d_in[1];
    const float* Wih = (const float*)d_in[2];
    const float* Whh = (const float*)d_in[3];
    const float* bih = (const float*)d_in[4];
    const float* bhh = (const float*)d_in[5];
    const float* Wfc = (const float*)d_in[6];
    const float* bfc = (const float*)d_in[7];
    float* out = (float*)d_out;

    static const int DYN_GEMM = 73728;
    static const int DYN_KA = 98304;   // gates 81920 / attn 98304 / fc 82944
    cudaFuncSetAttribute(k_pre, cudaFuncAttributeMaxDynamicSharedMemorySize, DYN_GEMM);
    cudaFuncSetAttribute(kA, cudaFuncAttributeMaxDynamicSharedMemorySize, DYN_KA);

    k_init<<<256, 256>>>();                       // 0
    k_convert<<<592, 256>>>(Wih, Whh, Wfc);       // 1
    k_pre<<<2048, 256, DYN_GEMM>>>(st, bih, bhh); // 2

    // 3: kA(0), 4: kA(1), 5: kA(2) <- ncu -s 5 profiles mixed gates+attn+fc
    for (int t = 0; t <= TT + 2; ++t) {
        int nG = (t < TT) ? 64 : 0;                      // gates+cell step t
        int nA = (t >= 1 && t <= TT) ? BB : 0;           // attention step t-1 (1 batch/CTA)
        int nP = (t >= 2 && t <= TT + 1) ? 32 : 0;       // fc partials step t-2
        int nR = (t >= 3) ? 16 : 0;                      // fc reduce step t-3
        kA<<<nG + nA + nP + nR, 256, DYN_KA>>>(t, nG, nA, nP, enc, bfc, out);
    }
}

// round 9
// speedup vs baseline: 2.0277x; 2.0277x over previous
#include <cuda_runtime.h>
#include <cuda_fp16.h>
#include <math.h>
#include <stdint.h>

#define BB 256
#define TT 32
#define SS 128
#define II 256
#define HH 1024
#define OO 256
#define G4 4096

// ---------------- scratch (static device globals; no allocation) ------------
__device__ float d_Xg[(size_t)TT * BB * G4];     // [T][B][4H] input gates + biases
__device__ float d_h[2][BB * HH];                // double-buffered hidden (fp32)
__device__ uint32_t d_h16[2][BB * 512];          // hidden, f16x2 words, frag-permuted
__device__ float d_c[BB * HH];
__device__ uint32_t d_u16[2][BB * 1024];         // [ctx|h] f16x2 words, permuted
__device__ float d_fcp[2][4][BB * OO];           // split-K FC partials
__device__ uint32_t d_Wih16[G4 * 128];           // fp16 pairs, word-permuted
__device__ uint32_t d_Whh16[(size_t)G4 * 512];
__device__ uint32_t d_Wfc16[OO * 1024];
__device__ uint32_t d_st16[8192 * 128];          // shifted_target fp16, m-major (t*256+b)

// ---------------- helpers ----------------------------------------------------
__device__ __forceinline__ uint32_t packf16(float a, float b) {
    __half2 h = __floats2half2_rn(a, b);
    return *reinterpret_cast<uint32_t*>(&h);
}
__device__ __forceinline__ uint32_t cvta_s(const void* p) {
    return (uint32_t)__cvta_generic_to_shared(p);
}
// permute word index within its 8-word group so (w, w+4) become adjacent
__device__ __forceinline__ int kperm(int k) {
    return (k & ~7) + ((k & 3) << 1) + ((k >> 2) & 1);
}
#define CPASYNC16(sa, g) asm volatile("cp.async.cg.shared.global [%0], [%1], 16;" :: "r"(sa), "l"(g))
#define CPCOMMIT() asm volatile("cp.async.commit_group;")
#define CPWAIT(n) asm volatile("cp.async.wait_group %0;" :: "n"(n))

__device__ __forceinline__ void mma_f16(float c[4], const uint32_t a[4], const uint32_t b[2]) {
    asm volatile(
        "mma.sync.aligned.m16n8k16.row.col.f32.f16.f16.f32 "
        "{%0,%1,%2,%3}, {%4,%5,%6,%7}, {%8,%9}, {%0,%1,%2,%3};"
        : "+f"(c[0]), "+f"(c[1]), "+f"(c[2]), "+f"(c[3])
        : "r"(a[0]), "r"(a[1]), "r"(a[2]), "r"(a[3]), "r"(b[0]), "r"(b[1]));
}

#define SIG(x) (1.f / (1.f + __expf(-(x))))

// ========== precompute GEMM (k_pre): 128x128 tiles, fp16, depth-2 ============
// K=256 elems = 128 words; chunk 32 words; 4 chunks.
// smem: As u32 [2][128][40] @0 (40960 B), Bs u32 [2][128][40] @40960 -> 81920 B
__device__ __forceinline__ void gemm_pre(
    int ctam, int ctan,
    const float* __restrict__ e1, const float* __restrict__ e2,
    float* __restrict__ Cout, char* dyn)
{
    uint32_t* As = (uint32_t*)dyn;
    uint32_t* Bs = (uint32_t*)(dyn + 40960);
    const int tid = threadIdx.x;
    const int lane = tid & 31;
    const int wid = tid >> 5;
    const int wm = wid & 3;
    const int wn = wid >> 2;
    const int tg = lane & 3;
    const int gpr = lane >> 2;

    float acc[2][8][4];
#pragma unroll
    for (int i = 0; i < 2; ++i)
#pragma unroll
        for (int j = 0; j < 8; ++j)
#pragma unroll
            for (int k = 0; k < 4; ++k) acc[i][j][k] = 0.f;

    auto stage = [&](int buf, int kcw) {
        // A: 128 rows x 32 words = 1024 x 16B, 4/thread
#pragma unroll
        for (int it = 0; it < 4; ++it) {
            int slot = it * 256 + tid;
            int row = slot >> 3;
            int cc = (slot & 7) << 2;
            CPASYNC16(cvta_s(As + buf * 5120 + row * 40 + cc),
                      d_st16 + (size_t)(ctam * 128 + row) * 128 + kcw + cc);
        }
#pragma unroll
        for (int it = 0; it < 4; ++it) {
            int slot = it * 256 + tid;
            int row = slot >> 3;
            int cc = (slot & 7) << 2;
            CPASYNC16(cvta_s(Bs + buf * 5120 + row * 40 + cc),
                      d_Wih16 + (size_t)(ctan * 128 + row) * 128 + kcw + cc);
        }
    };

    stage(0, 0);
    CPCOMMIT();
    const int nc = 4;
    for (int c = 0; c < nc; ++c) {
        if (c + 1 < nc) stage((c + 1) & 1, (c + 1) * 32);
        CPCOMMIT();
        CPWAIT(1);
        __syncthreads();
        const uint32_t* Af = As + (c & 1) * 5120;
        const uint32_t* Bf = Bs + (c & 1) * 5120;
#pragma unroll
        for (int ks = 0; ks < 4; ++ks) {
            uint32_t a[2][4], b[8][2];
#pragma unroll
            for (int mt = 0; mt < 2; ++mt) {
                int r = wm * 32 + mt * 16 + gpr;
                uint2 lo = *(const uint2*)(Af + r * 40 + ks * 8 + tg * 2);
                uint2 hi = *(const uint2*)(Af + (r + 8) * 40 + ks * 8 + tg * 2);
                a[mt][0] = lo.x; a[mt][2] = lo.y;
                a[mt][1] = hi.x; a[mt][3] = hi.y;
            }
#pragma unroll
            for (int nt = 0; nt < 8; ++nt) {
                int n = wn * 64 + nt * 8 + gpr;
                uint2 v = *(const uint2*)(Bf + n * 40 + ks * 8 + tg * 2);
                b[nt][0] = v.x; b[nt][1] = v.y;
            }
#pragma unroll
            for (int mt = 0; mt < 2; ++mt)
#pragma unroll
                for (int nt = 0; nt < 8; ++nt)
                    mma_f16(acc[mt][nt], a[mt], b[nt]);
        }
        __syncthreads();
    }
#pragma unroll
    for (int mt = 0; mt < 2; ++mt)
#pragma unroll
        for (int nt = 0; nt < 8; ++nt) {
            int gm0 = ctam * 128 + wm * 32 + mt * 16 + gpr;
            int gn = ctan * 128 + wn * 64 + nt * 8 + tg * 2;
#pragma unroll
            for (int half = 0; half < 2; ++half) {
                int gm = gm0 + half * 8;
                float v0 = acc[mt][nt][half * 2 + 0] + e1[gn] + e2[gn];
                float v1 = acc[mt][nt][half * 2 + 1] + e1[gn + 1] + e2[gn + 1];
                *(float2*)(Cout + (size_t)gm * G4 + gn) = make_float2(v0, v1);
            }
        }
}

// ========== fused gates GEMM + LSTM cell (fp16 fragments) =====================
// 128 CTAs = ctam(4) x ctan(32). CTA 64M x 128N (4 gates x 32 cols).
// K=1024 elems = 512 words; chunk 32 words (64 elems); 16 chunks; depth-3.
// smem: As u32 [3][64][40] @0 (30720 B), Bs u32 [3][128][40] @30720 -> 92160 B
// epilogue: ep fp32 [64][132] @0 (33792 B)
__device__ __forceinline__ void gatescell_dev(
    int ctam, int ctan,
    const uint32_t* __restrict__ hA,   // h_{t-1}, f16x2 permuted
    const float* __restrict__ Xg,
    float* __restrict__ hOut,
    uint32_t* __restrict__ hOut16,
    char* dyn)
{
    uint32_t* As = (uint32_t*)dyn;
    uint32_t* Bs = (uint32_t*)(dyn + 30720);
    const int tid = threadIdx.x;
    const int lane = tid & 31;
    const int wid = tid >> 5;
    const int wm = wid & 1;      // 2 M halves of 32 rows
    const int g = wid >> 1;      // warp owns one gate (0..3)
    const int tg = lane & 3;
    const int gpr = lane >> 2;
    const int q0 = ctan * 32;
    const int m0 = ctam * 64;

    float acc[2][4][4];
#pragma unroll
    for (int i = 0; i < 2; ++i)
#pragma unroll
        for (int j = 0; j < 4; ++j)
#pragma unroll
            for (int k = 0; k < 4; ++k) acc[i][j][k] = 0.f;

    auto stage = [&](int buf, int kcw) {
        // A: 64 x 32 words = 512 x 16B, 2/thread
#pragma unroll
        for (int it = 0; it < 2; ++it) {
            int slot = it * 256 + tid;
            int row = slot >> 3;
            int cc = (slot & 7) << 2;
            CPASYNC16(cvta_s(As + buf * 2560 + row * 40 + cc),
                      hA + (size_t)(m0 + row) * 512 + kcw + cc);
        }
        // B: 128 x 32 words = 1024 x 16B, 4/thread; rows gather 4 gate blocks
#pragma unroll
        for (int it = 0; it < 4; ++it) {
            int slot = it * 256 + tid;
            int row = slot >> 3;
            int cc = (slot & 7) << 2;
            int wr = (row >> 5) * HH + q0 + (row & 31);
            CPASYNC16(cvta_s(Bs + buf * 5120 + row * 40 + cc),
                      d_Whh16 + (size_t)wr * 512 + kcw + cc);
        }
    };

    stage(0, 0); CPCOMMIT();
    stage(1, 32); CPCOMMIT();
    const int nc = 16;
    for (int c = 0; c < nc; ++c) {
        if (c + 2 < nc) stage((c + 2) % 3, (c + 2) * 32);
        CPCOMMIT();
        CPWAIT(2);
        __syncthreads();
        const uint32_t* Af = As + (c % 3) * 2560;
        const uint32_t* Bf = Bs + (c % 3) * 5120;
#pragma unroll
        for (int ks = 0; ks < 4; ++ks) {
            uint32_t a[2][4], b[4][2];
#pragma unroll
            for (int mt = 0; mt < 2; ++mt) {
                int r = wm * 32 + mt * 16 + gpr;
                uint2 lo = *(const uint2*)(Af + r * 40 + ks * 8 + tg * 2);
                uint2 hi = *(const uint2*)(Af + (r + 8) * 40 + ks * 8 + tg * 2);
                a[mt][0] = lo.x; a[mt][2] = lo.y;
                a[mt][1] = hi.x; a[mt][3] = hi.y;
            }
#pragma unroll
            for (int nt = 0; nt < 4; ++nt) {
                int n = g * 32 + nt * 8 + gpr;
                uint2 v = *(const uint2*)(Bf + n * 40 + ks * 8 + tg * 2);
                b[nt][0] = v.x; b[nt][1] = v.y;
            }
#pragma unroll
            for (int mt = 0; mt < 2; ++mt)
#pragma unroll
                for (int nt = 0; nt < 4; ++nt)
                    mma_f16(acc[mt][nt], a[mt], b[nt]);
        }
        __syncthreads();
    }

    // gate exchange: ep[row 64][n 128], stride 132
    float* ep = (float*)dyn;
    __syncthreads();
#pragma unroll
    for (int mt = 0; mt < 2; ++mt)
#pragma unroll
        for (int nt = 0; nt < 4; ++nt) {
            int r0 = wm * 32 + mt * 16 + gpr;
            int col = g * 32 + nt * 8 + tg * 2;
            *(float2*)(ep + r0 * 132 + col) = make_float2(acc[mt][nt][0], acc[mt][nt][1]);
            *(float2*)(ep + (r0 + 8) * 132 + col) = make_float2(acc[mt][nt][2], acc[mt][nt][3]);
        }
    __syncthreads();

    // cell: 64 rows x 16 words (32 q) = 1024 words, 4 per thread
#pragma unroll
    for (int k = 0; k < 4; ++k) {
        int idx = k * 256 + tid;
        int row = idx >> 4;
        int wq = idx & 15;
        int b = m0 + row;
        int q = q0 + wq * 2;
        size_t xb = (size_t)b * G4 + q;
        float2 xi = *(const float2*)(Xg + xb);
        float2 xf = *(const float2*)(Xg + xb + HH);
        float2 xg = *(const float2*)(Xg + xb + 2 * HH);
        float2 xo = *(const float2*)(Xg + xb + 3 * HH);
        int qq = wq * 2;
        float2 ei = *(const float2*)(ep + row * 132 + qq);
        float2 ef = *(const float2*)(ep + row * 132 + 32 + qq);
        float2 eg = *(const float2*)(ep + row * 132 + 64 + qq);
        float2 eo = *(const float2*)(ep + row * 132 + 96 + qq);
        size_t hb = (size_t)b * HH + q;
        float2 c2 = *(const float2*)(d_c + hb);
        c2.x = SIG(ef.x + xf.x) * c2.x + SIG(ei.x + xi.x) * tanhf(eg.x + xg.x);
        c2.y = SIG(ef.y + xf.y) * c2.y + SIG(ei.y + xi.y) * tanhf(eg.y + xg.y);
        float h0 = SIG(eo.x + xo.x) * tanhf(c2.x);
        float h1 = SIG(eo.y + xo.y) * tanhf(c2.y);
        *(float2*)(d_c + hb) = c2;
        *(float2*)(hOut + hb) = make_float2(h0, h1);
        hOut16[(size_t)b * 512 + kperm((q0 >> 1) + wq)] = packf16(h0, h1);
    }
}

// ========== FC split-K partial GEMM (fp16) ====================================
// Tile 128M x 64N; slice = 512 elems = 256 words; chunk 32 words; 8 chunks; depth-3.
// smem: Af u32 [3][128][40] @0 (61440), Bf u32 [3][64][40] @61440 -> 92160 B
__device__ __forceinline__ void fcpart_dev(
    int ctam, int ctan, int kslice,
    const uint32_t* __restrict__ u16, float* __restrict__ part)
{
    extern __shared__ char dyn[];
    uint32_t* Af = (uint32_t*)dyn;
    uint32_t* Bf = (uint32_t*)(dyn + 61440);
    const int tid = threadIdx.x;
    const int lane = tid & 31;
    const int wid = tid >> 5;
    const int wm = wid & 3;
    const int wn = wid >> 2;
    const int tg = lane & 3;
    const int gpr = lane >> 2;
    const int k0w = kslice * 256;

    float acc[2][4][4];
#pragma unroll
    for (int i = 0; i < 2; ++i)
#pragma unroll
        for (int j = 0; j < 4; ++j)
#pragma unroll
            for (int k = 0; k < 4; ++k) acc[i][j][k] = 0.f;

    auto stage = [&](int buf, int kcw) {
#pragma unroll
        for (int it = 0; it < 4; ++it) {
            int slot = it * 256 + tid;
            int row = slot >> 3;
            int cc = (slot & 7) << 2;
            CPASYNC16(cvta_s(Af + buf * 5120 + row * 40 + cc),
                      u16 + (size_t)(ctam * 128 + row) * 1024 + k0w + kcw + cc);
        }
#pragma unroll
        for (int it = 0; it < 2; ++it) {
            int slot = it * 256 + tid;
            int row = slot >> 3;
            int cc = (slot & 7) << 2;
            CPASYNC16(cvta_s(Bf + buf * 2560 + row * 40 + cc),
                      d_Wfc16 + (size_t)(ctan * 64 + row) * 1024 + k0w + kcw + cc);
        }
    };

    stage(0, 0); CPCOMMIT();
    stage(1, 32); CPCOMMIT();
    const int nc = 8;
    for (int c = 0; c < nc; ++c) {
        if (c + 2 < nc) stage((c + 2) % 3, (c + 2) * 32);
        CPCOMMIT();
        CPWAIT(2);
        __syncthreads();
        const uint32_t* A = Af + (c % 3) * 5120;
        const uint32_t* B = Bf + (c % 3) * 2560;
#pragma unroll
        for (int ks = 0; ks < 4; ++ks) {
            uint32_t a[2][4], b[4][2];
#pragma unroll
            for (int mt = 0; mt < 2; ++mt) {
                int r = wm * 32 + mt * 16 + gpr;
                uint2 lo = *(const uint2*)(A + r * 40 + ks * 8 + tg * 2);
                uint2 hi = *(const uint2*)(A + (r + 8) * 40 + ks * 8 + tg * 2);
                a[mt][0] = lo.x; a[mt][2] = lo.y;
                a[mt][1] = hi.x; a[mt][3] = hi.y;
            }
#pragma unroll
            for (int nt = 0; nt < 4; ++nt) {
                int n = wn * 32 + nt * 8 + gpr;
                uint2 v = *(const uint2*)(B + n * 40 + ks * 8 + tg * 2);
                b[nt][0] = v.x; b[nt][1] = v.y;
            }
#pragma unroll
            for (int mt = 0; mt < 2; ++mt)
#pragma unroll
                for (int nt = 0; nt < 4; ++nt)
                    mma_f16(acc[mt][nt], a[mt], b[nt]);
        }
        __syncthreads();
    }
#pragma unroll
    for (int mt = 0; mt < 2; ++mt)
#pragma unroll
        for (int nt = 0; nt < 4; ++nt) {
            int gm0 = ctam * 128 + wm * 32 + mt * 16 + gpr;
            int gn = ctan * 64 + wn * 32 + nt * 8 + tg * 2;
            *(float2*)(part + (size_t)gm0 * OO + gn) =
                make_float2(acc[mt][nt][0], acc[mt][nt][1]);
            *(float2*)(part + (size_t)(gm0 + 8) * OO + gn) =
                make_float2(acc[mt][nt][2], acc[mt][nt][3]);
        }
}

// ========== attention (fp32, cp.async pipelined online softmax) ===============
__device__ __forceinline__ void attn_dev(int b, int tatt, const float* __restrict__ enc,
                                         const float* __restrict__ hcur,
                                         float* __restrict__ out, int par, char* dyn,
                                         float* s_scores, float* s_m, float* s_l)
{
    float* es = (float*)dyn;
    const int tid = threadIdx.x;
    const int lane = tid & 31;
    const int w = tid >> 5;

    const float* hb = hcur + (size_t)b * HH;
    float hreg[32];
#pragma unroll
    for (int i = 0; i < 32; ++i) hreg[i] = hb[i * 32 + lane];

    const float* encb = enc + (size_t)b * SS * HH;
#pragma unroll
    for (int p = 0; p < 3; ++p) {
        const float* gsrc = encb + (size_t)(w * 16 + p) * HH;
        float* sb = es + ((size_t)(p % 3) * 8 + w) * 1024;
#pragma unroll
        for (int q = 0; q < 8; ++q)
            CPASYNC16(cvta_s(sb + q * 128 + lane * 4), gsrc + q * 128 + lane * 4);
        CPCOMMIT();
    }

    float m = -1e30f, l = 0.f;
    float ctx[32];
#pragma unroll
    for (int i = 0; i < 32; ++i) ctx[i] = 0.f;

    for (int j = 0; j < 16; ++j) {
        CPWAIT(2);
        __syncwarp();
        const float* e = es + ((size_t)(j % 3) * 8 + w) * 1024;
        float dot = 0.f;
#pragma unroll
        for (int i = 0; i < 32; ++i) dot += hreg[i] * e[i * 32 + lane];
#pragma unroll
        for (int o = 16; o; o >>= 1) dot += __shfl_xor_sync(0xffffffffu, dot, o);
        if (lane == 0) s_scores[w * 16 + j] = dot;

        float nm = fmaxf(m, dot);
        float al = __expf(m - nm);
        float p = __expf(dot - nm);
        l = l * al + p;
#pragma unroll
        for (int i = 0; i < 32; ++i) ctx[i] = ctx[i] * al + p * e[i * 32 + lane];
        m = nm;
        __syncwarp();
        if (j + 3 < 16) {
            const float* gsrc = encb + (size_t)(w * 16 + j + 3) * HH;
            float* sb = es + ((size_t)(j % 3) * 8 + w) * 1024;
#pragma unroll
            for (int q = 0; q < 8; ++q)
                CPASYNC16(cvta_s(sb + q * 128 + lane * 4), gsrc + q * 128 + lane * 4);
        }
        CPCOMMIT();
    }
    CPWAIT(0);
    if (lane == 0) { s_m[w] = m; s_l[w] = l; }
    __syncthreads();

    float M = -1e30f;
#pragma unroll
    for (int i = 0; i < 8; ++i) M = fmaxf(M, s_m[i]);
    float L = 0.f;
#pragma unroll
    for (int i = 0; i < 8; ++i) L += s_l[i] * __expf(s_m[i] - M);

    float sc = __expf(m - M);
    float* cs = es + (size_t)w * 1024;
#pragma unroll
    for (int i = 0; i < 32; ++i) cs[i * 32 + lane] = ctx[i] * sc;
    __syncthreads();

    // write u = [ctx | h] as fp16 words, fragment-permuted
    uint32_t* ubuf = d_u16[par];
    for (int wI = tid; wI < 512; wI += 256) {
        float s0 = 0.f, s1 = 0.f;
#pragma unroll
        for (int ww = 0; ww < 8; ++ww) {
            s0 += es[(size_t)ww * 1024 + 2 * wI];
            s1 += es[(size_t)ww * 1024 + 2 * wI + 1];
        }
        ubuf[(size_t)b * 1024 + kperm(wI)] = packf16(s0 / L, s1 / L);
        ubuf[(size_t)b * 1024 + kperm(512 + wI)] = packf16(hb[2 * wI], hb[2 * wI + 1]);
    }
    if (tid < SS) {
        float p = __expf(s_scores[tid] - M) / L;
        out[(size_t)BB * TT * OO + (size_t)b * TT * SS + (size_t)tatt * SS + tid] = p;
    }
}

// ---------------- kernels -----------------------------------------------------
__global__ void k_init() {
    int g = blockIdx.x * 256 + threadIdx.x;  // 65536
    float4 z = make_float4(0.f, 0.f, 0.f, 0.f);
    ((float4*)d_h[1])[g] = z;
    ((float4*)d_c)[g] = z;
    if (g < 32768) ((uint4*)d_h16[1])[g] = make_uint4(0, 0, 0, 0);
}

__global__ void __launch_bounds__(256) k_convert(const float* __restrict__ st,
                                                 const float* __restrict__ Wih,
                                                 const float* __restrict__ Whh,
                                                 const float* __restrict__ Wfc) {
    int g = blockIdx.x * 256 + threadIdx.x;
    int stride = gridDim.x * 256;
    // Whh: 4096 rows x 512 words
    for (int i = g; i < G4 * 512; i += stride) {
        int n = i >> 9;
        int w = i & 511;
        d_Whh16[(size_t)n * 512 + kperm(w)] = packf16(Whh[(size_t)n * HH + 2 * w],
                                                      Whh[(size_t)n * HH + 2 * w + 1]);
    }
    // Wih: 4096 rows x 128 words
    for (int i = g; i < G4 * 128; i += stride) {
        int n = i >> 7;
        int w = i & 127;
        d_Wih16[n * 128 + kperm(w)] = packf16(Wih[(size_t)n * II + 2 * w],
                                              Wih[(size_t)n * II + 2 * w + 1]);
    }
    // Wfc: 256 rows x 1024 words
    for (int i = g; i < OO * 1024; i += stride) {
        int n = i >> 10;
        int w = i & 1023;
        d_Wfc16[n * 1024 + kperm(w)] = packf16(Wfc[(size_t)n * 2 * HH + 2 * w],
                                               Wfc[(size_t)n * 2 * HH + 2 * w + 1]);
    }
    // st: m-major (m = t*256 + b), 8192 rows x 128 words; t==0 rows are zero
    for (int i = g; i < 8192 * 128; i += stride) {
        int m = i >> 7;
        int w = i & 127;
        int t_ = m >> 8;
        int b_ = m & 255;
        uint32_t v = 0;
        if (t_ != 0) {
            const float* s = st + (size_t)b_ * TT * II + (size_t)t_ * II + 2 * w;
            v = packf16(s[0], s[1]);
        }
        d_st16[(size_t)m * 128 + kperm(w)] = v;
    }
}

__global__ void __launch_bounds__(256, 2) k_pre(const float* __restrict__ bih,
                                                const float* __restrict__ bhh) {
    extern __shared__ char dyn[];
    gemm_pre(blockIdx.x >> 5, blockIdx.x & 31, bih, bhh, d_Xg, dyn);
}

__global__ void __launch_bounds__(256, 2) kA(int t, int nG, int nA, int nP,
                                             const float* __restrict__ enc,
                                             const float* __restrict__ bfc,
                                             float* __restrict__ out) {
    extern __shared__ char dyn[];
    __shared__ float s_scores[SS];
    __shared__ float s_m[8], s_l[8];
    int bid = blockIdx.x;
    if (bid < nG) {
        gatescell_dev(bid >> 5, bid & 31,
                      d_h16[(t + 1) & 1], d_Xg + (size_t)t * BB * G4,
                      d_h[t & 1], d_h16[t & 1], dyn);
    } else if (bid < nG + nA) {
        // attention for step t-1: each CTA handles 2 batches
        int ta = t - 1;
        int b0 = (bid - nG) * 2;
#pragma unroll
        for (int sub = 0; sub < 2; ++sub) {
            attn_dev(b0 + sub, ta, enc, d_h[ta & 1], out, ta & 1, dyn,
                     s_scores, s_m, s_l);
            __syncthreads();
        }
    } else if (bid < nG + nA + nP) {
        int f = bid - nG - nA;     // 0..31
        int tfc = t - 2;
        int ks = f & 3;
        int ctan = (f >> 2) & 3;
        int ctam = f >> 4;
        fcpart_dev(ctam, ctan, ks, d_u16[tfc & 1], d_fcp[tfc & 1][ks]);
    } else {
        int tr = t - 3;
        const float* p0 = d_fcp[tr & 1][0];
        const float* p1 = d_fcp[tr & 1][1];
        const float* p2 = d_fcp[tr & 1][2];
        const float* p3 = d_fcp[tr & 1][3];
        int bidr = bid - nG - nA - nP;  // 0..15
        for (int e = bidr * 256 + threadIdx.x; e < BB * OO; e += 16 * 256) {
            int b = e >> 8;
            int o = e & 255;
            float v = p0[e] + p1[e] + p2[e] + p3[e] + bfc[o];
            out[(size_t)b * TT * OO + (size_t)tr * OO + o] = v;
        }
    }
}

// ---------------- launch --------------------------------------------------------
extern "C" void kernel_launch(void* const* d_in, const int* in_sizes, int n_in,
                              void* d_out, int out_size) {
    const float* st  = (const float*)d_in[0];
    const float* enc = (const float*)d_in[1];
    const float* Wih = (const float*)d_in[2];
    const float* Whh = (const float*)d_in[3];
    const float* bih = (const float*)d_in[4];
    const float* bhh = (const float*)d_in[5];
    const float* Wfc = (const float*)d_in[6];
    const float* bfc = (const float*)d_in[7];
    float* out = (float*)d_out;

    static const int DYN_PRE = 81920;
    static const int DYN_KA = 98304;   // gates 92160 / attn 98304 / fc 92160
    cudaFuncSetAttribute(k_pre, cudaFuncAttributeMaxDynamicSharedMemorySize, DYN_PRE);
    cudaFuncSetAttribute(kA, cudaFuncAttributeMaxDynamicSharedMemorySize, DYN_KA);

    k_init<<<256, 256>>>();                           // 0
    k_convert<<<592, 256>>>(st, Wih, Whh, Wfc);       // 1
    k_pre<<<2048, 256, DYN_PRE>>>(bih, bhh);          // 2

    // 3: kA(0), 4: kA(1), 5: kA(2) <- ncu -s 5 profiles mixed gates+attn+fc
    for (int t = 0; t <= TT + 2; ++t) {
        int nG = (t < TT) ? 128 : 0;                     // gates+cell step t
        int nA = (t >= 1 && t <= TT) ? 128 : 0;          // attention step t-1 (2/CTA)
        int nP = (t >= 2 && t <= TT + 1) ? 32 : 0;       // fc partials step t-2
        int nR = (t >= 3) ? 16 : 0;                      // fc reduce step t-3
        kA<<<nG + nA + nP + nR, 256, DYN_KA>>>(t, nG, nA, nP, enc, bfc, out);
    }
}